// round 3
// baseline (speedup 1.0000x reference)
#include <cuda_runtime.h>
#include <math.h>

// WaveNet collapsed to the last-sample 32-dim recurrence (k=0 tap only):
//   u_L = tanh(F_L x) * sigmoid(G_L x);  x = R_L u + u;  skip += S_L u
//   out = end2 @ relu(end1 @ relu(skip) + b1) + b2
//
// Kernel 1 (pack): transpose weights into lane-coalesced float4 layouts.
// Kernel 2 (main): grid=8 (batch), 288 threads.
//   warp 0      : single-warp shfl recurrence, state in registers,
//                 F/G register-double-buffered, zero barriers in the chain.
//   warps 1-8   : 256 skip channels (1/thread), consume u in 8-layer chunks,
//                 pipelined one chunk behind warp 0. Then the end1/end2 head.

#define NL   40
#define RC   32
#define SC   256
#define CIN  6
#define T_IN 8192
#define FULLM 0xffffffffu

// packed FGR: per layer 3072 floats: F[jg][lane][4] @0, G @1024, R @2048
__device__ float g_pk[NL * 3072];            // 491 KB
__device__ float g_skipT4[(NL * RC) * SC];   // [kg][c][4kk], 1.31 MB
__device__ float g_end1T4[SC * SC];          // [jg][c][4jj], 256 KB
__device__ float g_xs0[8 * RC];

// ---------------------------------------------------------------- pack
__global__ void wn_pack(const float* __restrict__ x,
                        const float* __restrict__ start_w,
                        const float* __restrict__ filter_w,
                        const float* __restrict__ gate_w,
                        const float* __restrict__ res_w,
                        const float* __restrict__ skip_w,
                        const float* __restrict__ end1_w)
{
    const int N1 = NL * 3072;          // 122880
    const int N2 = NL * RC * SC;       // 327680
    const int N3 = SC * SC;            // 65536
    const int total = N1 + N2 + N3 + 8 * RC;

    for (int idx = blockIdx.x * blockDim.x + threadIdx.x; idx < total;
         idx += gridDim.x * blockDim.x) {
        if (idx < N1) {
            int L  = idx / 3072;
            int r  = idx % 3072;
            int sec = r >> 10;             // 0=F 1=G 2=R
            int t  = r & 1023;
            int jg = t >> 7;
            int w  = t & 127;
            int i  = w >> 2;               // lane (output channel)
            int jj = w & 3;
            int j  = 4 * jg + jj;          // input channel
            float v;
            if (sec == 0)      v = filter_w[L * 2048 + i * 64 + j * 2];
            else if (sec == 1) v = gate_w  [L * 2048 + i * 64 + j * 2];
            else               v = res_w   [L * 1024 + i * 32 + j];
            g_pk[idx] = v;
        } else if (idx < N1 + N2) {
            int t  = idx - N1;
            int kg = t >> 10;
            int w  = t & 1023;
            int c  = w >> 2;
            int kk = w & 3;
            int k  = 4 * kg + kk;          // k = L*32 + j
            int L  = k >> 5, j = k & 31;
            g_skipT4[t] = skip_w[L * (SC * RC) + c * RC + j];
        } else if (idx < N1 + N2 + N3) {
            int t  = idx - N1 - N2;
            int jg = t >> 10;
            int w  = t & 1023;
            int c  = w >> 2;
            int jj = w & 3;
            g_end1T4[t] = end1_w[c * SC + 4 * jg + jj];
        } else {
            int t = idx - N1 - N2 - N3;
            int b = t / RC, i = t % RC;
            float s = 0.f;
            #pragma unroll
            for (int ci = 0; ci < CIN; ci++)
                s += start_w[i * CIN + ci] * x[(b * CIN + ci) * T_IN + (T_IN - 1)];
            g_xs0[b * RC + i] = s;
        }
    }
}

// ---------------------------------------------------------------- main
__global__ __launch_bounds__(288, 1)
void wn_main(const float* __restrict__ end1_b,
             const float* __restrict__ end2_w,
             const float* __restrict__ end2_b,
             float* __restrict__ out)
{
    const int b    = blockIdx.x;
    const int tid  = threadIdx.x;
    const int lane = tid & 31;
    const int warp = tid >> 5;

    __shared__ __align__(16) float us_all[NL * RC];  // 5.1 KB
    __shared__ __align__(16) float hs[SC];
    __shared__ float red8[8];

    // ---- warp-0 persistent recurrence state
    float x = 0.f;
    float4 FG[2][16];                    // [parity][F:0-7, G:8-15]
    if (warp == 0) {
        x = g_xs0[b * RC + lane];
        const float4* nb = (const float4*)g_pk + lane;   // layer 0
        #pragma unroll
        for (int q = 0; q < 16; q++) FG[0][q] = nb[q * 32];
    }

    float skip_acc = 0.f;                // skip threads: channel c = tid-32
    const int c = tid - 32;

    // ---- chunk pipeline: 5 compute chunks + 1 drain
    for (int chunk = 0; chunk < 6; chunk++) {
        if (warp == 0) {
            if (chunk < 5) {
                #pragma unroll
                for (int l = 0; l < 8; l++) {
                    const int L = chunk * 8 + l;
                    const int par = L & 1;
                    const float4* wb = (const float4*)g_pk + L * 768 + lane;

                    // R for this layer (consumed ~phase B)
                    float4 Rw[8];
                    #pragma unroll
                    for (int jg = 0; jg < 8; jg++) Rw[jg] = wb[512 + jg * 32];
                    // F/G for next layer (consumed next iteration)
                    if (L + 1 < NL) {
                        const float4* nb = wb + 768;
                        #pragma unroll
                        for (int q = 0; q < 16; q++) FG[par ^ 1][q] = nb[q * 32];
                    }

                    // phase A: f/g GEMV via shfl broadcast
                    float f0 = 0.f, f1 = 0.f, g0 = 0.f, g1 = 0.f;
                    #pragma unroll
                    for (int jg = 0; jg < 8; jg++) {
                        float xj0 = __shfl_sync(FULLM, x, 4 * jg + 0);
                        float xj1 = __shfl_sync(FULLM, x, 4 * jg + 1);
                        float xj2 = __shfl_sync(FULLM, x, 4 * jg + 2);
                        float xj3 = __shfl_sync(FULLM, x, 4 * jg + 3);
                        const float4 Fw = FG[par][jg];
                        const float4 Gw = FG[par][8 + jg];
                        f0 = fmaf(Fw.x, xj0, f0); f1 = fmaf(Fw.y, xj1, f1);
                        f0 = fmaf(Fw.z, xj2, f0); f1 = fmaf(Fw.w, xj3, f1);
                        g0 = fmaf(Gw.x, xj0, g0); g1 = fmaf(Gw.y, xj1, g1);
                        g0 = fmaf(Gw.z, xj2, g0); g1 = fmaf(Gw.w, xj3, g1);
                    }
                    float fv = f0 + f1, gv = g0 + g1;
                    float e2 = __expf(2.f * fv);
                    float t  = __fdividef(e2 - 1.f, e2 + 1.f);
                    float sg = __fdividef(1.f, 1.f + __expf(-gv));
                    float u  = t * sg;
                    us_all[L * RC + lane] = u;

                    // phase B: residual GEMV + state update
                    float r0 = 0.f, r1 = 0.f;
                    #pragma unroll
                    for (int jg = 0; jg < 8; jg++) {
                        float uj0 = __shfl_sync(FULLM, u, 4 * jg + 0);
                        float uj1 = __shfl_sync(FULLM, u, 4 * jg + 1);
                        float uj2 = __shfl_sync(FULLM, u, 4 * jg + 2);
                        float uj3 = __shfl_sync(FULLM, u, 4 * jg + 3);
                        const float4 Rv = Rw[jg];
                        r0 = fmaf(Rv.x, uj0, r0); r1 = fmaf(Rv.y, uj1, r1);
                        r0 = fmaf(Rv.z, uj2, r0); r1 = fmaf(Rv.w, uj3, r1);
                    }
                    x = r0 + r1 + u;
                }
            }
        } else if (chunk >= 1) {
            // skip GEMM for chunk-1: k in [256(chunk-1), 256 chunk)
            const int q = chunk - 1;
            const float4* sp = (const float4*)g_skipT4 + (64 * q) * 256 + c;
            const float*  up = us_all + 256 * q;
            #pragma unroll 8
            for (int kg = 0; kg < 64; kg++) {
                float4 s4 = sp[kg * 256];
                float4 u4 = *reinterpret_cast<const float4*>(up + 4 * kg);
                skip_acc = fmaf(s4.x, u4.x, fmaf(s4.y, u4.y,
                           fmaf(s4.z, u4.z, fmaf(s4.w, u4.w, skip_acc))));
            }
        }
        __syncthreads();
    }

    // ---- head (skip threads only)
    if (warp > 0) hs[c] = fmaxf(skip_acc, 0.f);
    __syncthreads();

    if (warp > 0) {
        const float4* ep = (const float4*)g_end1T4 + c;
        float e = end1_b[c];
        #pragma unroll 8
        for (int jg = 0; jg < 64; jg++) {
            float4 e4 = ep[jg * 256];
            float4 h4 = *reinterpret_cast<const float4*>(hs + 4 * jg);
            e = fmaf(e4.x, h4.x, fmaf(e4.y, h4.y,
                fmaf(e4.z, h4.z, fmaf(e4.w, h4.w, e))));
        }
        e = fmaxf(e, 0.f);
        float o = end2_w[c] * e;
        #pragma unroll
        for (int off = 16; off > 0; off >>= 1)
            o += __shfl_xor_sync(FULLM, o, off);
        if (lane == 0) red8[warp - 1] = o;
    }
    __syncthreads();
    if (tid == 0) {
        float tot = 0.f;
        #pragma unroll
        for (int w = 0; w < 8; w++) tot += red8[w];
        out[b] = tot + end2_b[0];
    }
}

extern "C" void kernel_launch(void* const* d_in, const int* in_sizes, int n_in,
                              void* d_out, int out_size)
{
    const float* x        = (const float*)d_in[0];
    const float* start_w  = (const float*)d_in[1];
    const float* filter_w = (const float*)d_in[2];
    const float* gate_w   = (const float*)d_in[3];
    const float* res_w    = (const float*)d_in[4];
    const float* skip_w   = (const float*)d_in[5];
    const float* end1_w   = (const float*)d_in[6];
    const float* end1_b   = (const float*)d_in[7];
    const float* end2_w   = (const float*)d_in[8];
    const float* end2_b   = (const float*)d_in[9];
    float* out = (float*)d_out;

    wn_pack<<<1009, 512>>>(x, start_w, filter_w, gate_w, res_w, skip_w, end1_w);
    wn_main<<<8, 288>>>(end1_b, end2_w, end2_b, out);
}

// round 4
// speedup vs baseline: 1.1518x; 1.1518x over previous
#include <cuda_runtime.h>
#include <math.h>

// WaveNet collapsed to the last-sample 32-dim recurrence (k=0 tap only):
//   u_L = tanh(F_L x) * sigmoid(G_L x);  x = R_L u + u;  skip += S_L u
//   out = end2 @ relu(end1 @ relu(skip) + b1) + b2
//
// 3 launches:
//  1) wn_pack : lane-coalesced float4 weight layouts + start-conv states.
//  2) wn_rec  : ONE block, 8 warps (warp = batch). Per-warp recurrence with
//               smem-broadcast state (LDS.128, no shfl), weights via LDG
//               (leader warp L2, followers L1). 2 warps/SMSP hide latency.
//               Writes all u vectors to global.
//  3) wn_head : grid=8, the skip GEMM (K=1280) + end1/end2 head.

#define NL   40
#define RC   32
#define SC   256
#define CIN  6
#define T_IN 8192
#define FULLM 0xffffffffu

// packed FGR: per layer 3072 floats: F[jg][lane][4] @0, G @1024, R @2048
__device__ float g_pk[NL * 3072];            // 491 KB
__device__ float g_skipT4[(NL * RC) * SC];   // [kg][c][4kk], 1.31 MB
__device__ float g_end1T4[SC * SC];          // [jg][c][4jj], 256 KB
__device__ float g_xs0[8 * RC];
__device__ float g_us[8 * NL * RC];          // u activations, 40 KB

// ---------------------------------------------------------------- pack
__global__ void wn_pack(const float* __restrict__ x,
                        const float* __restrict__ start_w,
                        const float* __restrict__ filter_w,
                        const float* __restrict__ gate_w,
                        const float* __restrict__ res_w,
                        const float* __restrict__ skip_w,
                        const float* __restrict__ end1_w)
{
    const int N1 = NL * 3072;          // 122880
    const int N2 = NL * RC * SC;       // 327680
    const int N3 = SC * SC;            // 65536
    const int total = N1 + N2 + N3 + 8 * RC;

    for (int idx = blockIdx.x * blockDim.x + threadIdx.x; idx < total;
         idx += gridDim.x * blockDim.x) {
        if (idx < N1) {
            int L  = idx / 3072;
            int r  = idx % 3072;
            int sec = r >> 10;             // 0=F 1=G 2=R
            int t  = r & 1023;
            int jg = t >> 7;
            int w  = t & 127;
            int i  = w >> 2;               // lane (output channel)
            int jj = w & 3;
            int j  = 4 * jg + jj;          // input channel
            float v;
            if (sec == 0)      v = filter_w[L * 2048 + i * 64 + j * 2];
            else if (sec == 1) v = gate_w  [L * 2048 + i * 64 + j * 2];
            else               v = res_w   [L * 1024 + i * 32 + j];
            g_pk[idx] = v;
        } else if (idx < N1 + N2) {
            int t  = idx - N1;
            int kg = t >> 10;
            int w  = t & 1023;
            int c  = w >> 2;
            int kk = w & 3;
            int k  = 4 * kg + kk;          // k = L*32 + j
            int L  = k >> 5, j = k & 31;
            g_skipT4[t] = skip_w[L * (SC * RC) + c * RC + j];
        } else if (idx < N1 + N2 + N3) {
            int t  = idx - N1 - N2;
            int jg = t >> 10;
            int w  = t & 1023;
            int c  = w >> 2;
            int jj = w & 3;
            g_end1T4[t] = end1_w[c * SC + 4 * jg + jj];
        } else {
            int t = idx - N1 - N2 - N3;
            int b = t / RC, i = t % RC;
            float s = 0.f;
            #pragma unroll
            for (int ci = 0; ci < CIN; ci++)
                s += start_w[i * CIN + ci] * x[(b * CIN + ci) * T_IN + (T_IN - 1)];
            g_xs0[b * RC + i] = s;
        }
    }
}

// ---------------------------------------------------------------- recurrence
__global__ __launch_bounds__(256, 1)
void wn_rec()
{
    const int tid  = threadIdx.x;
    const int lane = tid & 31;
    const int b    = tid >> 5;          // warp = batch

    __shared__ __align__(16) float xs[8][RC];   // per-batch state
    __shared__ __align__(16) float uss[8][RC];  // per-batch u (for broadcast)

    xs[b][lane] = g_xs0[b * RC + lane];
    __syncwarp();

    float* us_out = g_us + b * (NL * RC) + lane;

    for (int L = 0; L < NL; L++) {
        const float4* wb = (const float4*)g_pk + L * 768 + lane;

        // ---- weight loads: 24 independent LDG.128 (leader: L2, rest: L1)
        float4 F[8], G[8], R[8];
        #pragma unroll
        for (int jg = 0; jg < 8; jg++) F[jg] = wb[jg * 32];
        #pragma unroll
        for (int jg = 0; jg < 8; jg++) G[jg] = wb[256 + jg * 32];
        #pragma unroll
        for (int jg = 0; jg < 8; jg++) R[jg] = wb[512 + jg * 32];

        // ---- phase A: f/g GEMV, x broadcast via uniform-address LDS.128
        float f0 = 0.f, f1 = 0.f, g0 = 0.f, g1 = 0.f;
        #pragma unroll
        for (int jg = 0; jg < 8; jg++) {
            const float4 xv = *reinterpret_cast<const float4*>(&xs[b][4 * jg]);
            f0 = fmaf(F[jg].x, xv.x, f0); f1 = fmaf(F[jg].y, xv.y, f1);
            f0 = fmaf(F[jg].z, xv.z, f0); f1 = fmaf(F[jg].w, xv.w, f1);
            g0 = fmaf(G[jg].x, xv.x, g0); g1 = fmaf(G[jg].y, xv.y, g1);
            g0 = fmaf(G[jg].z, xv.z, g0); g1 = fmaf(G[jg].w, xv.w, g1);
        }
        const float fv = f0 + f1, gv = g0 + g1;
        const float e2 = __expf(2.f * fv);
        const float t  = __fdividef(e2 - 1.f, e2 + 1.f);
        const float sg = __fdividef(1.f, 1.f + __expf(-gv));
        const float u  = t * sg;

        uss[b][lane] = u;
        us_out[L * RC] = u;
        __syncwarp();

        // ---- phase B: residual GEMV, u broadcast via LDS.128
        float r0 = 0.f, r1 = 0.f;
        #pragma unroll
        for (int jg = 0; jg < 8; jg++) {
            const float4 uv = *reinterpret_cast<const float4*>(&uss[b][4 * jg]);
            r0 = fmaf(R[jg].x, uv.x, r0); r1 = fmaf(R[jg].y, uv.y, r1);
            r0 = fmaf(R[jg].z, uv.z, r0); r1 = fmaf(R[jg].w, uv.w, r1);
        }
        xs[b][lane] = r0 + r1 + u;
        __syncwarp();
    }
}

// ---------------------------------------------------------------- head
__global__ __launch_bounds__(256, 1)
void wn_head(const float* __restrict__ end1_b,
             const float* __restrict__ end2_w,
             const float* __restrict__ end2_b,
             float* __restrict__ out)
{
    const int b    = blockIdx.x;
    const int tid  = threadIdx.x;
    const int lane = tid & 31;
    const int warp = tid >> 5;

    __shared__ __align__(16) float us[NL * RC];   // 5.1 KB
    __shared__ __align__(16) float hs[SC];
    __shared__ float red8[8];

    #pragma unroll
    for (int i = tid; i < NL * RC; i += 256) us[i] = g_us[b * (NL * RC) + i];
    __syncthreads();

    // ---- skip GEMM: skip[c] = sum_k S_T[c][k] u[k], K = 1280
    {
        float acc = 0.f;
        const float4* sp = (const float4*)g_skipT4 + tid;
        #pragma unroll 8
        for (int kg = 0; kg < 320; kg++) {
            const float4 s4 = sp[kg * 256];
            const float4 u4 = *reinterpret_cast<const float4*>(&us[4 * kg]);
            acc = fmaf(s4.x, u4.x, fmaf(s4.y, u4.y,
                  fmaf(s4.z, u4.z, fmaf(s4.w, u4.w, acc))));
        }
        hs[tid] = fmaxf(acc, 0.f);
    }
    __syncthreads();

    // ---- end1 + end2
    {
        const float4* ep = (const float4*)g_end1T4 + tid;
        float e = end1_b[tid];
        #pragma unroll 8
        for (int jg = 0; jg < 64; jg++) {
            const float4 e4 = ep[jg * 256];
            const float4 h4 = *reinterpret_cast<const float4*>(&hs[4 * jg]);
            e = fmaf(e4.x, h4.x, fmaf(e4.y, h4.y,
                fmaf(e4.z, h4.z, fmaf(e4.w, h4.w, e))));
        }
        e = fmaxf(e, 0.f);
        float o = end2_w[tid] * e;
        #pragma unroll
        for (int off = 16; off > 0; off >>= 1)
            o += __shfl_xor_sync(FULLM, o, off);
        if (lane == 0) red8[warp] = o;
    }
    __syncthreads();
    if (tid == 0) {
        float tot = 0.f;
        #pragma unroll
        for (int w = 0; w < 8; w++) tot += red8[w];
        out[b] = tot + end2_b[0];
    }
}

extern "C" void kernel_launch(void* const* d_in, const int* in_sizes, int n_in,
                              void* d_out, int out_size)
{
    const float* x        = (const float*)d_in[0];
    const float* start_w  = (const float*)d_in[1];
    const float* filter_w = (const float*)d_in[2];
    const float* gate_w   = (const float*)d_in[3];
    const float* res_w    = (const float*)d_in[4];
    const float* skip_w   = (const float*)d_in[5];
    const float* end1_w   = (const float*)d_in[6];
    const float* end1_b   = (const float*)d_in[7];
    const float* end2_w   = (const float*)d_in[8];
    const float* end2_b   = (const float*)d_in[9];
    float* out = (float*)d_out;

    wn_pack<<<1009, 512>>>(x, start_w, filter_w, gate_w, res_w, skip_w, end1_w);
    wn_rec<<<1, 256>>>();
    wn_head<<<8, 256>>>(end1_b, end2_w, end2_b, out);
}

// round 5
// speedup vs baseline: 1.4155x; 1.2290x over previous
#include <cuda_runtime.h>
#include <math.h>

// WaveNet collapsed to the last-sample 32-dim recurrence (k=0 tap only):
//   u_L = tanh(F_L x) * sigmoid(G_L x);  x = R_L u + u;  skip += S_L u
//   out = end2 @ relu(end1 @ relu(skip) + b1) + b2
//
// 2 launches:
//  1) wn_pack : lane-coalesced float4 weight layouts + start-conv states.
//  2) wn_main : grid=8 (batch), 256 thr.
//     warp 0    : register double-buffered recurrence (prefetch distance 1,
//                 compile-time buffer parity), smem LDS.128 broadcasts.
//     warps 1-7 : 256 skip channels (32 threads dual-mapped), consuming u in
//                 8-layer chunks one chunk behind warp 0; then end1/end2 head.

#define NL   40
#define RC   32
#define SC   256
#define CIN  6
#define T_IN 8192
#define FULLM 0xffffffffu

// packed FGR: per layer 3072 floats: F[jg][lane][4] @0, G @1024, R @2048
__device__ float g_pk[NL * 3072];            // 491 KB
__device__ float g_skipT4[(NL * RC) * SC];   // [kg][c][4kk], 1.31 MB
__device__ float g_end1T4[SC * SC];          // [jg][c][4jj], 256 KB
__device__ float g_xs0[8 * RC];

// ---------------------------------------------------------------- pack
__global__ void wn_pack(const float* __restrict__ x,
                        const float* __restrict__ start_w,
                        const float* __restrict__ filter_w,
                        const float* __restrict__ gate_w,
                        const float* __restrict__ res_w,
                        const float* __restrict__ skip_w,
                        const float* __restrict__ end1_w)
{
    const int N1 = NL * 3072;          // 122880
    const int N2 = NL * RC * SC;       // 327680
    const int N3 = SC * SC;            // 65536
    const int total = N1 + N2 + N3 + 8 * RC;

    for (int idx = blockIdx.x * blockDim.x + threadIdx.x; idx < total;
         idx += gridDim.x * blockDim.x) {
        if (idx < N1) {
            int L  = idx / 3072;
            int r  = idx % 3072;
            int sec = r >> 10;             // 0=F 1=G 2=R
            int t  = r & 1023;
            int jg = t >> 7;
            int w  = t & 127;
            int i  = w >> 2;               // lane (output channel)
            int jj = w & 3;
            int j  = 4 * jg + jj;          // input channel
            float v;
            if (sec == 0)      v = filter_w[L * 2048 + i * 64 + j * 2];
            else if (sec == 1) v = gate_w  [L * 2048 + i * 64 + j * 2];
            else               v = res_w   [L * 1024 + i * 32 + j];
            g_pk[idx] = v;
        } else if (idx < N1 + N2) {
            int t  = idx - N1;
            int kg = t >> 10;
            int w  = t & 1023;
            int c  = w >> 2;
            int kk = w & 3;
            int k  = 4 * kg + kk;          // k = L*32 + j
            int L  = k >> 5, j = k & 31;
            g_skipT4[t] = skip_w[L * (SC * RC) + c * RC + j];
        } else if (idx < N1 + N2 + N3) {
            int t  = idx - N1 - N2;
            int jg = t >> 10;
            int w  = t & 1023;
            int c  = w >> 2;
            int jj = w & 3;
            g_end1T4[t] = end1_w[c * SC + 4 * jg + jj];
        } else {
            int t = idx - N1 - N2 - N3;
            int b = t / RC, i = t % RC;
            float s = 0.f;
            #pragma unroll
            for (int ci = 0; ci < CIN; ci++)
                s += start_w[i * CIN + ci] * x[(b * CIN + ci) * T_IN + (T_IN - 1)];
            g_xs0[b * RC + i] = s;
        }
    }
}

// ---------------------------------------------------------------- main
__global__ __launch_bounds__(256, 1)
void wn_main(const float* __restrict__ end1_b,
             const float* __restrict__ end2_w,
             const float* __restrict__ end2_b,
             float* __restrict__ out)
{
    const int b    = blockIdx.x;
    const int tid  = threadIdx.x;
    const int lane = tid & 31;
    const int warp = tid >> 5;

    __shared__ __align__(16) float us_all[NL * RC];   // 5.1 KB
    __shared__ __align__(16) float xs[RC];
    __shared__ __align__(16) float hs[SC];
    __shared__ float red8[8];

    // skip-thread channel mapping: warps 1-7 -> c0 in [0,224);
    // warp 1 (tid 32..63) additionally owns c1 in [224,256).
    const int  c0   = tid - 32;
    const bool dual = (warp == 1);
    const int  c1   = tid + 192;
    float acc0 = 0.f, acc1 = 0.f;

    // ---- warp-0 persistent double-buffered weights
    float4 Fb[2][8], Gb[2][8], Rb[2][8];
    if (warp == 0) {
        xs[lane] = g_xs0[b * RC + lane];
        const float4* nb = (const float4*)g_pk + lane;     // layer 0
        #pragma unroll
        for (int jg = 0; jg < 8; jg++) {
            Fb[0][jg] = nb[jg * 32];
            Gb[0][jg] = nb[256 + jg * 32];
            Rb[0][jg] = nb[512 + jg * 32];
        }
        __syncwarp();
    }

    // ---- chunk pipeline: 5 compute chunks + 1 drain
    for (int chunk = 0; chunk < 6; chunk++) {
        if (warp == 0) {
            if (chunk < 5) {
                #pragma unroll
                for (int l = 0; l < 8; l++) {
                    const int L   = chunk * 8 + l;
                    const int par = l & 1;              // compile-time

                    // prefetch layer L+1 into the other buffer (issue first)
                    if (L + 1 < NL) {
                        const float4* nb = (const float4*)g_pk + (L + 1) * 768 + lane;
                        #pragma unroll
                        for (int jg = 0; jg < 8; jg++) {
                            Fb[par ^ 1][jg] = nb[jg * 32];
                            Gb[par ^ 1][jg] = nb[256 + jg * 32];
                            Rb[par ^ 1][jg] = nb[512 + jg * 32];
                        }
                    }

                    // phase A: f/g GEMV, x broadcast via uniform LDS.128
                    float f0 = 0.f, f1 = 0.f, f2 = 0.f, f3 = 0.f;
                    float g0 = 0.f, g1 = 0.f, g2 = 0.f, g3 = 0.f;
                    #pragma unroll
                    for (int jg = 0; jg < 8; jg++) {
                        const float4 xv = *reinterpret_cast<const float4*>(&xs[4 * jg]);
                        const float4 Fw = Fb[par][jg];
                        const float4 Gw = Gb[par][jg];
                        f0 = fmaf(Fw.x, xv.x, f0); f1 = fmaf(Fw.y, xv.y, f1);
                        f2 = fmaf(Fw.z, xv.z, f2); f3 = fmaf(Fw.w, xv.w, f3);
                        g0 = fmaf(Gw.x, xv.x, g0); g1 = fmaf(Gw.y, xv.y, g1);
                        g2 = fmaf(Gw.z, xv.z, g2); g3 = fmaf(Gw.w, xv.w, g3);
                    }
                    const float fv = (f0 + f1) + (f2 + f3);
                    const float gv = (g0 + g1) + (g2 + g3);
                    const float e2 = __expf(2.f * fv);
                    const float t  = __fdividef(e2 - 1.f, e2 + 1.f);
                    const float sg = __fdividef(1.f, 1.f + __expf(-gv));
                    const float u  = t * sg;
                    us_all[L * RC + lane] = u;
                    __syncwarp();

                    // phase B: residual GEMV, u broadcast via uniform LDS.128
                    float r0 = 0.f, r1 = 0.f, r2 = 0.f, r3 = 0.f;
                    #pragma unroll
                    for (int jg = 0; jg < 8; jg++) {
                        const float4 uv = *reinterpret_cast<const float4*>(&us_all[L * RC + 4 * jg]);
                        const float4 Rv = Rb[par][jg];
                        r0 = fmaf(Rv.x, uv.x, r0); r1 = fmaf(Rv.y, uv.y, r1);
                        r2 = fmaf(Rv.z, uv.z, r2); r3 = fmaf(Rv.w, uv.w, r3);
                    }
                    xs[lane] = (r0 + r1) + (r2 + r3) + u;
                    __syncwarp();
                }
            }
        } else if (chunk >= 1) {
            // skip GEMM for chunk-1: k in [256(chunk-1), 256 chunk)
            const int q = chunk - 1;
            const float4* sp = (const float4*)g_skipT4 + (64 * q) * 256;
            const float*  up = us_all + 256 * q;
            #pragma unroll 8
            for (int kg = 0; kg < 64; kg++) {
                const float4 u4 = *reinterpret_cast<const float4*>(up + 4 * kg);
                const float4 s4 = sp[kg * 256 + c0];
                acc0 = fmaf(s4.x, u4.x, fmaf(s4.y, u4.y,
                       fmaf(s4.z, u4.z, fmaf(s4.w, u4.w, acc0))));
                if (dual) {
                    const float4 s4b = sp[kg * 256 + c1];
                    acc1 = fmaf(s4b.x, u4.x, fmaf(s4b.y, u4.y,
                           fmaf(s4b.z, u4.z, fmaf(s4b.w, u4.w, acc1))));
                }
            }
        }
        __syncthreads();
    }

    // ---- head
    if (warp > 0) {
        hs[c0] = fmaxf(acc0, 0.f);
        if (dual) hs[c1] = fmaxf(acc1, 0.f);
    }
    __syncthreads();

    float o = 0.f;
    if (warp > 0) {
        float e0 = end1_b[c0];
        float e1 = dual ? end1_b[c1] : 0.f;
        const float4* ep = (const float4*)g_end1T4;
        #pragma unroll 8
        for (int jg = 0; jg < 64; jg++) {
            const float4 h4 = *reinterpret_cast<const float4*>(&hs[4 * jg]);
            const float4 a4 = ep[jg * 256 + c0];
            e0 = fmaf(a4.x, h4.x, fmaf(a4.y, h4.y,
                 fmaf(a4.z, h4.z, fmaf(a4.w, h4.w, e0))));
            if (dual) {
                const float4 b4 = ep[jg * 256 + c1];
                e1 = fmaf(b4.x, h4.x, fmaf(b4.y, h4.y,
                     fmaf(b4.z, h4.z, fmaf(b4.w, h4.w, e1))));
            }
        }
        o = end2_w[c0] * fmaxf(e0, 0.f);
        if (dual) o += end2_w[c1] * fmaxf(e1, 0.f);
    }
    #pragma unroll
    for (int off = 16; off > 0; off >>= 1)
        o += __shfl_xor_sync(FULLM, o, off);
    if (lane == 0) red8[warp] = o;
    __syncthreads();
    if (tid == 0) {
        float tot = 0.f;
        #pragma unroll
        for (int w = 0; w < 8; w++) tot += red8[w];
        out[b] = tot + end2_b[0];
    }
}

extern "C" void kernel_launch(void* const* d_in, const int* in_sizes, int n_in,
                              void* d_out, int out_size)
{
    const float* x        = (const float*)d_in[0];
    const float* start_w  = (const float*)d_in[1];
    const float* filter_w = (const float*)d_in[2];
    const float* gate_w   = (const float*)d_in[3];
    const float* res_w    = (const float*)d_in[4];
    const float* skip_w   = (const float*)d_in[5];
    const float* end1_w   = (const float*)d_in[6];
    const float* end1_b   = (const float*)d_in[7];
    const float* end2_w   = (const float*)d_in[8];
    const float* end2_b   = (const float*)d_in[9];
    float* out = (float*)d_out;

    wn_pack<<<1009, 512>>>(x, start_w, filter_w, gate_w, res_w, skip_w, end1_w);
    wn_main<<<8, 256>>>(end1_b, end2_w, end2_b, out);
}

// round 6
// speedup vs baseline: 1.6468x; 1.1634x over previous
#include <cuda_runtime.h>
#include <math.h>

// WaveNet collapsed to the last-sample 32-dim recurrence (k=0 tap only):
//   u_L = tanh(F_L x) * sigmoid(G_L x);  x = R_L u + u;  skip += S_L u
//   out = end2 @ relu(end1 @ relu(skip) + b1) + b2
//
// 2 launches:
//  1) wn_pack : lane-coalesced float4 weight layouts + start-conv states.
//  2) wn_main : grid=8 (batch), 256 thr, 96KB dynamic smem weight ring.
//     warp 0    : recurrence from SMEM (LDS.128 only, f32x2 packed FMAs,
//                 ~60 live regs, no spills, no LDG in the chain).
//     warps 1-7 : weight producers (chunk q+1 -> smem ring) + 256 skip
//                 channels consuming u one 4-layer chunk behind; then head.

#define NL   40
#define RC   32
#define SC   256
#define CIN  6
#define T_IN 8192
#define FULLM 0xffffffffu

#define CH   4                 // layers per chunk
#define NCH  (NL / CH)         // 10 chunks
#define LW   768               // float4 per layer (3072 floats: F@0 G@256 R@512)
#define CW   (CH * LW)         // float4 per chunk
#define RING_BYTES (2 * CW * 16)   // 98304

typedef unsigned long long u64;

__device__ float g_pk[NL * 3072];            // packed F/G/R, 491 KB
__device__ float g_skipT4[(NL * RC) * SC];   // [kg][c][4kk], 1.31 MB
__device__ float g_end1T4[SC * SC];          // [jg][c][4jj], 256 KB
__device__ float g_xs0[8 * RC];

__device__ __forceinline__ void fma2(u64& d, u64 a, u64 b) {
    asm("fma.rn.f32x2 %0, %1, %2, %3;" : "=l"(d) : "l"(a), "l"(b), "l"(d));
}
__device__ __forceinline__ float2 upk(u64 v) {
    float2 r; asm("mov.b64 {%0, %1}, %2;" : "=f"(r.x), "=f"(r.y) : "l"(v));
    return r;
}

// ---------------------------------------------------------------- pack
__global__ void wn_pack(const float* __restrict__ x,
                        const float* __restrict__ start_w,
                        const float* __restrict__ filter_w,
                        const float* __restrict__ gate_w,
                        const float* __restrict__ res_w,
                        const float* __restrict__ skip_w,
                        const float* __restrict__ end1_w)
{
    const int N1 = NL * 3072;          // 122880
    const int N2 = NL * RC * SC;       // 327680
    const int N3 = SC * SC;            // 65536
    const int total = N1 + N2 + N3 + 8 * RC;

    for (int idx = blockIdx.x * blockDim.x + threadIdx.x; idx < total;
         idx += gridDim.x * blockDim.x) {
        if (idx < N1) {
            int L  = idx / 3072;
            int r  = idx % 3072;
            int sec = r >> 10;             // 0=F 1=G 2=R
            int t  = r & 1023;
            int jg = t >> 7;
            int w  = t & 127;
            int i  = w >> 2;               // lane (output channel)
            int jj = w & 3;
            int j  = 4 * jg + jj;          // input channel
            float v;
            if (sec == 0)      v = filter_w[L * 2048 + i * 64 + j * 2];
            else if (sec == 1) v = gate_w  [L * 2048 + i * 64 + j * 2];
            else               v = res_w   [L * 1024 + i * 32 + j];
            g_pk[idx] = v;
        } else if (idx < N1 + N2) {
            int t  = idx - N1;
            int kg = t >> 10;
            int w  = t & 1023;
            int c  = w >> 2;
            int kk = w & 3;
            int k  = 4 * kg + kk;          // k = L*32 + j
            int L  = k >> 5, j = k & 31;
            g_skipT4[t] = skip_w[L * (SC * RC) + c * RC + j];
        } else if (idx < N1 + N2 + N3) {
            int t  = idx - N1 - N2;
            int jg = t >> 10;
            int w  = t & 1023;
            int c  = w >> 2;
            int jj = w & 3;
            g_end1T4[t] = end1_w[c * SC + 4 * jg + jj];
        } else {
            int t = idx - N1 - N2 - N3;
            int b = t / RC, i = t % RC;
            float s = 0.f;
            #pragma unroll
            for (int ci = 0; ci < CIN; ci++)
                s += start_w[i * CIN + ci] * x[(b * CIN + ci) * T_IN + (T_IN - 1)];
            g_xs0[b * RC + i] = s;
        }
    }
}

// ---------------------------------------------------------------- main
extern __shared__ float ring[];    // RING_BYTES dynamic smem

__global__ __launch_bounds__(256, 1)
void wn_main(const float* __restrict__ end1_b,
             const float* __restrict__ end2_w,
             const float* __restrict__ end2_b,
             float* __restrict__ out)
{
    const int b    = blockIdx.x;
    const int tid  = threadIdx.x;
    const int lane = tid & 31;
    const int warp = tid >> 5;

    __shared__ __align__(16) float us_all[NL * RC];   // 5.1 KB
    __shared__ __align__(16) float xs[RC];
    __shared__ __align__(16) float hs[SC];
    __shared__ float red8[8];

    // skip-thread channel mapping: warps 1-7 -> c0 in [0,224);
    // warp 1 additionally owns c1 in [224,256).
    const int  c0   = tid - 32;
    const bool dual = (warp == 1);
    const int  c1   = tid + 192;
    float acc0 = 0.f, acc1 = 0.f;

    // ---- prologue: all threads stage chunk 0's weights; warp 0 loads state
    {
        const float4* src = (const float4*)g_pk;
        float4*       dst = (float4*)ring;
        #pragma unroll
        for (int i = tid; i < CW; i += 256) dst[i] = src[i];
    }
    if (warp == 0) xs[lane] = g_xs0[b * RC + lane];
    __syncthreads();

    // ---- chunk pipeline: NCH compute chunks + 1 drain
    for (int q = 0; q <= NCH; q++) {
        if (warp == 0) {
            if (q < NCH) {
                const float4* wc = (const float4*)ring + (q & 1) * CW;
                #pragma unroll
                for (int l = 0; l < CH; l++) {
                    const int L = q * CH + l;
                    const float4* wl = wc + l * LW + lane;

                    // phase A: f/g GEMV (smem LDS.128 + packed f32x2 FMA)
                    u64 fa = 0ull, fb = 0ull, ga = 0ull, gb = 0ull;
                    #pragma unroll
                    for (int jg = 0; jg < 8; jg++) {
                        const ulonglong2 xv = *(const ulonglong2*)&xs[4 * jg];
                        const ulonglong2 Fw = *(const ulonglong2*)(wl + jg * 32);
                        const ulonglong2 Gw = *(const ulonglong2*)(wl + 256 + jg * 32);
                        fma2(fa, Fw.x, xv.x); fma2(fb, Fw.y, xv.y);
                        fma2(ga, Gw.x, xv.x); fma2(gb, Gw.y, xv.y);
                    }
                    const float2 fpa = upk(fa), fpb = upk(fb);
                    const float2 gpa = upk(ga), gpb = upk(gb);
                    const float fv = (fpa.x + fpa.y) + (fpb.x + fpb.y);
                    const float gv = (gpa.x + gpa.y) + (gpb.x + gpb.y);
                    const float e2 = __expf(2.f * fv);
                    const float t  = __fdividef(e2 - 1.f, e2 + 1.f);
                    const float sg = __fdividef(1.f, 1.f + __expf(-gv));
                    const float u  = t * sg;
                    us_all[L * RC + lane] = u;
                    __syncwarp();

                    // phase B: residual GEMV
                    u64 ra = 0ull, rb = 0ull;
                    #pragma unroll
                    for (int jg = 0; jg < 8; jg++) {
                        const ulonglong2 uv = *(const ulonglong2*)&us_all[L * RC + 4 * jg];
                        const ulonglong2 Rw = *(const ulonglong2*)(wl + 512 + jg * 32);
                        fma2(ra, Rw.x, uv.x); fma2(rb, Rw.y, uv.y);
                    }
                    const float2 rpa = upk(ra), rpb = upk(rb);
                    xs[lane] = (rpa.x + rpa.y) + (rpb.x + rpb.y) + u;
                    __syncwarp();
                }
            }
        } else {
            // producers: stage chunk q+1's weights into the other ring slot
            if (q + 1 < NCH) {
                const float4* src = (const float4*)g_pk + (q + 1) * CW;
                float4*       dst = (float4*)ring + ((q + 1) & 1) * CW;
                for (int i = tid - 32; i < CW; i += 224) dst[i] = src[i];
            }
            // skip GEMM for chunk q-1: 32 k-groups
            if (q >= 1) {
                const int cq = q - 1;
                const float4* sp = (const float4*)g_skipT4 + (32 * cq) * 256;
                const float*  up = us_all + cq * (CH * RC);
                #pragma unroll
                for (int kg = 0; kg < 32; kg++) {
                    const float4 u4 = *reinterpret_cast<const float4*>(up + 4 * kg);
                    const float4 s4 = sp[kg * 256 + c0];
                    acc0 = fmaf(s4.x, u4.x, fmaf(s4.y, u4.y,
                           fmaf(s4.z, u4.z, fmaf(s4.w, u4.w, acc0))));
                    if (dual) {
                        const float4 s4b = sp[kg * 256 + c1];
                        acc1 = fmaf(s4b.x, u4.x, fmaf(s4b.y, u4.y,
                               fmaf(s4b.z, u4.z, fmaf(s4b.w, u4.w, acc1))));
                    }
                }
            }
        }
        __syncthreads();
    }

    // ---- head
    if (warp > 0) {
        hs[c0] = fmaxf(acc0, 0.f);
        if (dual) hs[c1] = fmaxf(acc1, 0.f);
    }
    __syncthreads();

    float o = 0.f;
    if (warp > 0) {
        float e0 = end1_b[c0];
        float e1 = dual ? end1_b[c1] : 0.f;
        const float4* ep = (const float4*)g_end1T4;
        #pragma unroll 8
        for (int jg = 0; jg < 64; jg++) {
            const float4 h4 = *reinterpret_cast<const float4*>(&hs[4 * jg]);
            const float4 a4 = ep[jg * 256 + c0];
            e0 = fmaf(a4.x, h4.x, fmaf(a4.y, h4.y,
                 fmaf(a4.z, h4.z, fmaf(a4.w, h4.w, e0))));
            if (dual) {
                const float4 b4 = ep[jg * 256 + c1];
                e1 = fmaf(b4.x, h4.x, fmaf(b4.y, h4.y,
                     fmaf(b4.z, h4.z, fmaf(b4.w, h4.w, e1))));
            }
        }
        o = end2_w[c0] * fmaxf(e0, 0.f);
        if (dual) o += end2_w[c1] * fmaxf(e1, 0.f);
    }
    #pragma unroll
    for (int off = 16; off > 0; off >>= 1)
        o += __shfl_xor_sync(FULLM, o, off);
    if (lane == 0) red8[warp] = o;
    __syncthreads();
    if (tid == 0) {
        float tot = 0.f;
        #pragma unroll
        for (int w = 0; w < 8; w++) tot += red8[w];
        out[b] = tot + end2_b[0];
    }
}

extern "C" void kernel_launch(void* const* d_in, const int* in_sizes, int n_in,
                              void* d_out, int out_size)
{
    const float* x        = (const float*)d_in[0];
    const float* start_w  = (const float*)d_in[1];
    const float* filter_w = (const float*)d_in[2];
    const float* gate_w   = (const float*)d_in[3];
    const float* res_w    = (const float*)d_in[4];
    const float* skip_w   = (const float*)d_in[5];
    const float* end1_w   = (const float*)d_in[6];
    const float* end1_b   = (const float*)d_in[7];
    const float* end2_w   = (const float*)d_in[8];
    const float* end2_b   = (const float*)d_in[9];
    float* out = (float*)d_out;

    static bool attr_set = false;
    if (!attr_set) {
        cudaFuncSetAttribute(wn_main,
                             cudaFuncAttributeMaxDynamicSharedMemorySize,
                             RING_BYTES);
        attr_set = true;
    }

    wn_pack<<<1009, 512>>>(x, start_w, filter_w, gate_w, res_w, skip_w, end1_w);
    wn_main<<<8, 256, RING_BYTES>>>(end1_b, end2_w, end2_b, out);
}

// round 7
// speedup vs baseline: 1.8624x; 1.1309x over previous
#include <cuda_runtime.h>
#include <math.h>

// WaveNet collapsed to the last-sample 32-dim recurrence (k=0 tap only):
//   u_L = tanh(F_L x) * sigmoid(G_L x);  x = R_L u + u;  skip += S_L u
//   out = end2 @ relu(end1 @ relu(skip) + b1) + b2
//
// 2 launches:
//  1) wn_pack : float4-vectorized weight repack. F is pre-scaled by -2 and G
//     by -1 so both activations are pure sigmoid chains in the main kernel.
//  2) wn_main : grid=8 (batch), 256 thr, 96KB dynamic smem weight ring.
//     warp 0    : recurrence from SMEM (LDS.128 + f32x2 FMAs).
//     warps 1-7 : BATCHED ring producers (reg-batched LDG, one latency
//                 exposure per chunk) + 256 skip channels one chunk behind;
//                 then the end1/end2 head.

#define NL   40
#define RC   32
#define SC   256
#define CIN  6
#define T_IN 8192
#define FULLM 0xffffffffu

#define CH   4                 // layers per chunk
#define NCH  (NL / CH)         // 10 chunks
#define LW   768               // float4 per layer (3072 floats: F@0 G@256 R@512)
#define CW   (CH * LW)         // float4 per chunk = 3072
#define RING_BYTES (2 * CW * 16)   // 98304

typedef unsigned long long u64;

__device__ float g_pk[NL * 3072];            // packed F'(-2F)/G'(-G)/R, 491 KB
__device__ float g_skipT4[(NL * RC) * SC];   // [kg][c][4kk], 1.31 MB
__device__ float g_end1T4[SC * SC];          // [jg][c][4jj], 256 KB
__device__ float g_xs0[8 * RC];

__device__ __forceinline__ void fma2(u64& d, u64 a, u64 b) {
    asm("fma.rn.f32x2 %0, %1, %2, %3;" : "=l"(d) : "l"(a), "l"(b), "l"(d));
}
__device__ __forceinline__ void add2(u64& d, u64 a, u64 b) {
    asm("add.rn.f32x2 %0, %1, %2;" : "=l"(d) : "l"(a), "l"(b));
}
__device__ __forceinline__ float2 upk(u64 v) {
    float2 r; asm("mov.b64 {%0, %1}, %2;" : "=f"(r.x), "=f"(r.y) : "l"(v));
    return r;
}

// ---------------------------------------------------------------- pack
// float4 work items:
//   [0, NA)        : g_pk     (NA = NL*768 = 30720)
//   [NA, NA+NB)    : g_skipT4 (NB = 81920)
//   [.., +NC)      : g_end1T4 (NC = 16384)
//   then 256 scalar items for g_xs0
__global__ void wn_pack(const float* __restrict__ x,
                        const float* __restrict__ start_w,
                        const float* __restrict__ filter_w,
                        const float* __restrict__ gate_w,
                        const float* __restrict__ res_w,
                        const float* __restrict__ skip_w,
                        const float* __restrict__ end1_w)
{
    const int NA = NL * LW;            // 30720
    const int NB = NL * RC * SC / 4;   // 81920
    const int NC = SC * SC / 4;        // 16384
    const int total = NA + NB + NC + 8 * RC;

    for (int idx = blockIdx.x * blockDim.x + threadIdx.x; idx < total;
         idx += gridDim.x * blockDim.x) {
        if (idx < NA) {
            int L  = idx / LW;
            int r  = idx % LW;
            int sec = r >> 8;              // 0=F 1=G 2=R
            int t  = r & 255;
            int jg = t >> 5;
            int i  = t & 31;
            float4 o;
            if (sec < 2) {
                const float* src = (sec ? gate_w : filter_w)
                                   + L * 2048 + i * 64 + 8 * jg;
                const float4 a = *(const float4*)src;
                const float4 c = *(const float4*)(src + 4);
                const float sc = sec ? -1.f : -2.f;
                o.x = sc * a.x; o.y = sc * a.z; o.z = sc * c.x; o.w = sc * c.z;
            } else {
                o = *(const float4*)(res_w + L * 1024 + i * 32 + 4 * jg);
            }
            ((float4*)g_pk)[idx] = o;
        } else if (idx < NA + NB) {
            int t  = idx - NA;
            int kg = t >> 8;
            int c  = t & 255;
            int L  = kg >> 3;
            int j0 = (kg & 7) * 4;
            ((float4*)g_skipT4)[t] =
                *(const float4*)(skip_w + L * (SC * RC) + c * RC + j0);
        } else if (idx < NA + NB + NC) {
            int t  = idx - NA - NB;
            int jg = t >> 8;
            int c  = t & 255;
            ((float4*)g_end1T4)[t] = *(const float4*)(end1_w + c * SC + 4 * jg);
        } else {
            int t = idx - NA - NB - NC;
            int b = t / RC, i = t % RC;
            float s = 0.f;
            #pragma unroll
            for (int ci = 0; ci < CIN; ci++)
                s += start_w[i * CIN + ci] * x[(b * CIN + ci) * T_IN + (T_IN - 1)];
            g_xs0[b * RC + i] = s;
        }
    }
}

// ---------------------------------------------------------------- main
extern __shared__ float ring[];    // RING_BYTES dynamic smem

__global__ __launch_bounds__(256, 1)
void wn_main(const float* __restrict__ end1_b,
             const float* __restrict__ end2_w,
             const float* __restrict__ end2_b,
             float* __restrict__ out)
{
    const int b    = blockIdx.x;
    const int tid  = threadIdx.x;
    const int lane = tid & 31;
    const int warp = tid >> 5;

    __shared__ __align__(16) float us_all[NL * RC];   // 5.1 KB
    __shared__ __align__(16) float xs[RC];
    __shared__ __align__(16) float hs[SC];
    __shared__ float red8[8];

    // skip-thread channel mapping: warps 1-7 -> c0 in [0,224);
    // warp 1 additionally owns c1 in [224,256).
    const int  c0   = tid - 32;
    const bool dual = (warp == 1);
    const int  c1   = tid + 192;
    float acc0 = 0.f, acc1 = 0.f;

    // ---- prologue: batched copy of chunk 0 (12 float4 each, exact)
    {
        const float4* src = (const float4*)g_pk;
        float4*       dst = (float4*)ring;
        float4 t[12];
        #pragma unroll
        for (int k = 0; k < 12; k++) t[k] = src[tid + 256 * k];
        #pragma unroll
        for (int k = 0; k < 12; k++) dst[tid + 256 * k] = t[k];
    }
    if (warp == 0) xs[lane] = g_xs0[b * RC + lane];
    __syncthreads();

    // ---- chunk pipeline: NCH compute chunks + 1 drain
    for (int q = 0; q <= NCH; q++) {
        if (warp == 0) {
            if (q < NCH) {
                const float4* wc = (const float4*)ring + (q & 1) * CW;
                #pragma unroll
                for (int l = 0; l < CH; l++) {
                    const int L = q * CH + l;
                    const float4* wl = wc + l * LW + lane;

                    // phase A: f'/g' GEMV (F'=-2F, G'=-G baked in)
                    u64 fa = 0ull, fb = 0ull, ga = 0ull, gb = 0ull;
                    #pragma unroll
                    for (int jg = 0; jg < 8; jg++) {
                        const ulonglong2 xv = *(const ulonglong2*)&xs[4 * jg];
                        const ulonglong2 Fw = *(const ulonglong2*)(wl + jg * 32);
                        const ulonglong2 Gw = *(const ulonglong2*)(wl + 256 + jg * 32);
                        fma2(fa, Fw.x, xv.x); fma2(fb, Fw.y, xv.y);
                        fma2(ga, Gw.x, xv.x); fma2(gb, Gw.y, xv.y);
                    }
                    add2(fa, fa, fb);
                    add2(ga, ga, gb);
                    const float2 fp = upk(fa);
                    const float2 gp = upk(ga);
                    const float fv = fp.x + fp.y;     // = -2f
                    const float gv = gp.x + gp.y;     // = -g
                    // t = 2*sig1 - 1, sig1 = 1/(1+e^{-2f});  u = t*sig2
                    const float a1 = __fdividef(1.f, 1.f + __expf(fv));
                    const float b1 = __fdividef(1.f, 1.f + __expf(gv));
                    const float u  = fmaf(a1 + a1, b1, -b1);
                    us_all[L * RC + lane] = u;
                    __syncwarp();

                    // phase B: residual GEMV
                    u64 ra = 0ull, rb = 0ull;
                    #pragma unroll
                    for (int jg = 0; jg < 8; jg++) {
                        const ulonglong2 uv = *(const ulonglong2*)&us_all[L * RC + 4 * jg];
                        const ulonglong2 Rw = *(const ulonglong2*)(wl + 512 + jg * 32);
                        fma2(ra, Rw.x, uv.x); fma2(rb, Rw.y, uv.y);
                    }
                    add2(ra, ra, rb);
                    const float2 rp = upk(ra);
                    xs[lane] = rp.x + rp.y + u;
                    __syncwarp();
                }
            }
        } else {
            // producers: BATCHED stage of chunk q+1 into the other ring slot
            if (q + 1 < NCH) {
                const float4* src = (const float4*)g_pk + (q + 1) * CW;
                float4*       dst = (float4*)ring + ((q + 1) & 1) * CW;
                const int t0 = tid - 32;           // 0..223
                float4 t[14];
                #pragma unroll
                for (int k = 0; k < 14; k++) {
                    const int i = t0 + 224 * k;
                    if (i < CW) t[k] = src[i];
                }
                #pragma unroll
                for (int k = 0; k < 14; k++) {
                    const int i = t0 + 224 * k;
                    if (i < CW) dst[i] = t[k];
                }
            }
            // skip GEMM for chunk q-1: 32 k-groups (fully unrolled -> batched)
            if (q >= 1) {
                const int cq = q - 1;
                const float4* sp = (const float4*)g_skipT4 + (32 * cq) * 256;
                const float*  up = us_all + cq * (CH * RC);
                #pragma unroll
                for (int kg = 0; kg < 32; kg++) {
                    const float4 u4 = *reinterpret_cast<const float4*>(up + 4 * kg);
                    const float4 s4 = sp[kg * 256 + c0];
                    acc0 = fmaf(s4.x, u4.x, fmaf(s4.y, u4.y,
                           fmaf(s4.z, u4.z, fmaf(s4.w, u4.w, acc0))));
                    if (dual) {
                        const float4 s4b = sp[kg * 256 + c1];
                        acc1 = fmaf(s4b.x, u4.x, fmaf(s4b.y, u4.y,
                               fmaf(s4b.z, u4.z, fmaf(s4b.w, u4.w, acc1))));
                    }
                }
            }
        }
        __syncthreads();
    }

    // ---- head
    if (warp > 0) {
        hs[c0] = fmaxf(acc0, 0.f);
        if (dual) hs[c1] = fmaxf(acc1, 0.f);
    }
    __syncthreads();

    float o = 0.f;
    if (warp > 0) {
        float e0 = end1_b[c0];
        float e1 = dual ? end1_b[c1] : 0.f;
        const float4* ep = (const float4*)g_end1T4;
        #pragma unroll 8
        for (int jg = 0; jg < 64; jg++) {
            const float4 h4 = *reinterpret_cast<const float4*>(&hs[4 * jg]);
            const float4 a4 = ep[jg * 256 + c0];
            e0 = fmaf(a4.x, h4.x, fmaf(a4.y, h4.y,
                 fmaf(a4.z, h4.z, fmaf(a4.w, h4.w, e0))));
            if (dual) {
                const float4 b4 = ep[jg * 256 + c1];
                e1 = fmaf(b4.x, h4.x, fmaf(b4.y, h4.y,
                     fmaf(b4.z, h4.z, fmaf(b4.w, h4.w, e1))));
            }
        }
        o = end2_w[c0] * fmaxf(e0, 0.f);
        if (dual) o += end2_w[c1] * fmaxf(e1, 0.f);
    }
    #pragma unroll
    for (int off = 16; off > 0; off >>= 1)
        o += __shfl_xor_sync(FULLM, o, off);
    if (lane == 0) red8[warp] = o;
    __syncthreads();
    if (tid == 0) {
        float tot = 0.f;
        #pragma unroll
        for (int w = 0; w < 8; w++) tot += red8[w];
        out[b] = tot + end2_b[0];
    }
}

extern "C" void kernel_launch(void* const* d_in, const int* in_sizes, int n_in,
                              void* d_out, int out_size)
{
    const float* x        = (const float*)d_in[0];
    const float* start_w  = (const float*)d_in[1];
    const float* filter_w = (const float*)d_in[2];
    const float* gate_w   = (const float*)d_in[3];
    const float* res_w    = (const float*)d_in[4];
    const float* skip_w   = (const float*)d_in[5];
    const float* end1_w   = (const float*)d_in[6];
    const float* end1_b   = (const float*)d_in[7];
    const float* end2_w   = (const float*)d_in[8];
    const float* end2_b   = (const float*)d_in[9];
    float* out = (float*)d_out;

    cudaFuncSetAttribute(wn_main,
                         cudaFuncAttributeMaxDynamicSharedMemorySize,
                         RING_BYTES);

    wn_pack<<<253, 512>>>(x, start_w, filter_w, gate_w, res_w, skip_w, end1_w);
    wn_main<<<8, 256, RING_BYTES>>>(end1_b, end2_w, end2_b, out);
}